// round 2
// baseline (speedup 1.0000x reference)
#include <cuda_runtime.h>
#include <math.h>

// Problem constants (fixed by setup_inputs)
#define N_NODES 4096
#define IN_DIM  512
#define H_DIM   256
#define OUTD    64
#define MAXDEG  192          // mean deg ~64, sigma ~8; 192 = ~16 sigma headroom
#define EPSV    1e-8f
#define A_SCAD  3.7f
#define PROP_STEP 4

static const float LAMF = (float)(1.0 / 0.9 - 1.0);   // 1/LAM_HAT - 1

// ---------------- device scratch (static, no allocation) ----------------
__device__ float g_dsq[N_NODES];
__device__ int   g_cnt[N_NODES];
__device__ int   g_cols[N_NODES * MAXDEG];
__device__ float g_y   [N_NODES * MAXDEG];
__device__ float g_Fu  [N_NODES * OUTD];
__device__ float g_F0  [N_NODES * OUTD];
__device__ float g_FA  [N_NODES * OUTD];
__device__ float g_FB  [N_NODES * OUTD];
__device__ float g_H   [N_NODES * H_DIM];
__device__ unsigned g_hist0[256];
__device__ unsigned g_hist [512];      // two 256-bin histograms (rank k, rank k+1)
__device__ unsigned g_prefix[2];
__device__ int      g_rank[2];
__device__ float    g_frac;
__device__ float    g_lamc;
__device__ int      g_M;
__device__ int      g_ticket;

// ---------------- reset ----------------
__global__ void reset_kernel() {
    g_M = 0;
    g_ticket = 0;
}

// ---------------- build padded adjacency (deterministic, column-sorted) ----
__global__ __launch_bounds__(256) void build_kernel(const float* __restrict__ A) {
    __shared__ unsigned char sbit[N_NODES];
    __shared__ int scnt[256];
    int row = blockIdx.x, tid = threadIdx.x;
    const float* Arow = A + (size_t)row * N_NODES;
    for (int i = tid; i < N_NODES; i += 256) sbit[i] = (Arow[i] != 0.0f);
    __syncthreads();
    int c0 = tid * 16;
    int cnt = 0;
#pragma unroll
    for (int c = 0; c < 16; c++) cnt += sbit[c0 + c];
    scnt[tid] = cnt;
    __syncthreads();
    // inclusive Hillis-Steele scan over 256 thread counts
    for (int off = 1; off < 256; off <<= 1) {
        int v = (tid >= off) ? scnt[tid - off] : 0;
        __syncthreads();
        scnt[tid] += v;
        __syncthreads();
    }
    int base  = scnt[tid] - cnt;
    int total = scnt[255];
    int pos = base;
    for (int c = 0; c < 16; c++)
        if (sbit[c0 + c] && pos < MAXDEG) g_cols[row * MAXDEG + (pos++)] = c0 + c;
    if (tid == 0) {
        int t = min(total, MAXDEG);
        g_cnt[row] = t;
        g_dsq[row] = sqrtf((float)(total + 1));   // D = deg + self-loop
        atomicAdd(&g_M, t);
    }
}

// ---------------- fp32 tiled GEMM: C = act(A[MxK] @ B[KxN] + bias) ----------
template <bool RELU>
__global__ __launch_bounds__(256) void gemm64(const float* __restrict__ A,
                                              const float* __restrict__ B,
                                              const float* __restrict__ bias,
                                              float* __restrict__ C,
                                              int M, int N, int K) {
    __shared__ float As[16][64];   // [k][m]
    __shared__ float Bs[16][64];   // [k][n]
    int tid = threadIdx.x;
    int tx = tid & 15, ty = tid >> 4;
    int row0 = blockIdx.y * 64, col0 = blockIdx.x * 64;
    float acc[4][4];
#pragma unroll
    for (int i = 0; i < 4; i++)
#pragma unroll
        for (int j = 0; j < 4; j++) acc[i][j] = 0.0f;

    int ar = tid >> 2, ak = (tid & 3) * 4;      // A tile: 64 rows x 16 k
    int bk = tid >> 4, bc = (tid & 15) * 4;     // B tile: 16 k x 64 cols

    for (int k0 = 0; k0 < K; k0 += 16) {
        float4 av = *(const float4*)&A[(size_t)(row0 + ar) * K + k0 + ak];
        float4 bv = *(const float4*)&B[(size_t)(k0 + bk) * N + col0 + bc];
        __syncthreads();
        As[ak + 0][ar] = av.x; As[ak + 1][ar] = av.y;
        As[ak + 2][ar] = av.z; As[ak + 3][ar] = av.w;
        *(float4*)&Bs[bk][bc] = bv;
        __syncthreads();
#pragma unroll
        for (int kk = 0; kk < 16; kk++) {
            float4 a = *(float4*)&As[kk][ty * 4];
            float4 b = *(float4*)&Bs[kk][tx * 4];
            float avr[4] = {a.x, a.y, a.z, a.w};
            float bvr[4] = {b.x, b.y, b.z, b.w};
#pragma unroll
            for (int i = 0; i < 4; i++)
#pragma unroll
                for (int j = 0; j < 4; j++) acc[i][j] = fmaf(avr[i], bvr[j], acc[i][j]);
        }
    }
#pragma unroll
    for (int i = 0; i < 4; i++) {
        int r = row0 + ty * 4 + i;
        float4 o;
        o.x = acc[i][0] + bias[col0 + tx * 4 + 0];
        o.y = acc[i][1] + bias[col0 + tx * 4 + 1];
        o.z = acc[i][2] + bias[col0 + tx * 4 + 2];
        o.w = acc[i][3] + bias[col0 + tx * 4 + 3];
        if (RELU) {
            o.x = fmaxf(o.x, 0.0f); o.y = fmaxf(o.y, 0.0f);
            o.z = fmaxf(o.z, 0.0f); o.w = fmaxf(o.w, 0.0f);
        }
        *(float4*)&C[(size_t)r * N + col0 + tx * 4] = o;
    }
}

// ---------------- row normalize: Fu = (Fc/dsq) / max(||Fc/dsq||, EPS) -------
__global__ __launch_bounds__(64) void normalize_kernel(const float* __restrict__ Fc) {
    int row = blockIdx.x, t = threadIdx.x;
    if (row == 0) {           // zero hist0 for this iteration's y pass
        for (int i = t; i < 256; i += 64) g_hist0[i] = 0;
    }
    float d = g_dsq[row];
    float v = Fc[row * OUTD + t] / d;
    float s = v * v;
#pragma unroll
    for (int o = 16; o; o >>= 1) s += __shfl_xor_sync(0xffffffffu, s, o);
    __shared__ float sh[2];
    if ((t & 31) == 0) sh[t >> 5] = s;
    __syncthreads();
    float nrm = sqrtf(sh[0] + sh[1]);
    g_Fu[row * OUTD + t] = v / fmaxf(nrm, EPSV);
}

// ---------------- per-edge y = clip(1 - Fu_i . Fu_j) + top-byte histogram ---
__global__ __launch_bounds__(128) void ycompute_kernel() {
    __shared__ float fu[OUTD];
    __shared__ unsigned hist[256];
    int row = blockIdx.x, tid = threadIdx.x;
    int lane = tid & 31, warp = tid >> 5;
    if (tid < OUTD) fu[tid] = g_Fu[row * OUTD + tid];
    for (int i = tid; i < 256; i += 128) hist[i] = 0;
    __syncthreads();
    int cnt = g_cnt[row];
    for (int s = warp; s < MAXDEG; s += 4) {
        float yv;
        if (s < cnt) {
            int j = g_cols[row * MAXDEG + s];
            float p = fu[lane] * g_Fu[j * OUTD + lane]
                    + fu[lane + 32] * g_Fu[j * OUTD + lane + 32];
#pragma unroll
            for (int o = 16; o; o >>= 1) p += __shfl_xor_sync(0xffffffffu, p, o);
            yv = fminf(fmaxf(1.0f - p, 0.0f), 2.0f);
        } else {
            yv = __int_as_float(0x7f800000);   // +inf padding: sorts past all real y
        }
        if (lane == 0) {
            g_y[row * MAXDEG + s] = yv;
            atomicAdd(&hist[__float_as_uint(yv) >> 24], 1u);
        }
    }
    __syncthreads();
    for (int i = tid; i < 256; i += 128)
        if (hist[i]) atomicAdd(&g_hist0[i], hist[i]);
}

// ---------------- radix-select init: consume hist0 (bits 31:24) -------------
__global__ void init_select_kernel() {
    if (threadIdx.x == 0) {
        int M = g_M;
        double idx = 0.75 * (double)(M - 1);
        long   k0  = (long)floor(idx);
        g_frac = (float)(idx - (double)k0);
        int R[2];
        R[0] = (int)k0;
        long k1 = k0 + 1; if (k1 > (long)(M - 1)) k1 = M - 1;
        R[1] = (int)k1;
        for (int t = 0; t < 2; t++) {
            int r = R[t]; unsigned cum = 0; int b = 255;
            for (int bb = 0; bb < 256; bb++) {
                unsigned c = g_hist0[bb];
                if (cum + c > (unsigned)r) { b = bb; break; }
                cum += c;
            }
            g_prefix[t] = (unsigned)b << 24;
            g_rank[t]   = r - (int)cum;
        }
    }
    for (int i = threadIdx.x; i < 512; i += blockDim.x) g_hist[i] = 0;
}

// ---------------- radix-select round (bits SHIFT+7 : SHIFT) -----------------
template <int SHIFT>
__global__ __launch_bounds__(256) void sel_kernel(const float* __restrict__ lg0,
                                                  const float* __restrict__ rdec,
                                                  const float* __restrict__ ralpha,
                                                  int kiter) {
    __shared__ unsigned h[512];
    int tid = threadIdx.x;
    for (int i = tid; i < 512; i += 256) h[i] = 0;
    __syncthreads();
    const unsigned hm = (SHIFT == 16) ? 0xFF000000u
                       : (SHIFT == 8) ? 0xFFFF0000u : 0xFFFFFF00u;
    unsigned p0 = g_prefix[0], p1 = g_prefix[1];
    const int T = N_NODES * MAXDEG;
    for (int s = blockIdx.x * 256 + tid; s < T; s += gridDim.x * 256) {
        unsigned u = __float_as_uint(g_y[s]);
        unsigned b = (u >> SHIFT) & 0xFFu;
        if ((u & hm) == p0) atomicAdd(&h[b], 1u);
        if ((u & hm) == p1) atomicAdd(&h[256 + b], 1u);
    }
    __syncthreads();
    for (int i = tid; i < 512; i += 256)
        if (h[i]) atomicAdd(&g_hist[i], h[i]);
    __threadfence();
    __shared__ int slast;
    if (tid == 0) slast = (atomicAdd(&g_ticket, 1) == (int)gridDim.x - 1);
    __syncthreads();
    if (!slast) return;
    if (tid == 0) {
        for (int t = 0; t < 2; t++) {
            int r = g_rank[t]; unsigned cum = 0; int b = 255;
            for (int bb = 0; bb < 256; bb++) {
                unsigned c = g_hist[t * 256 + bb];
                if (cum + c > (unsigned)r) { b = bb; break; }
                cum += c;
            }
            g_prefix[t] |= (unsigned)b << SHIFT;
            g_rank[t]    = r - (int)cum;
        }
        g_ticket = 0;
        if (SHIFT == 0) {
            float v0 = __uint_as_float(g_prefix[0]);
            float v1 = __uint_as_float(g_prefix[1]);
            float fr = g_frac;
            float gd = v0 * (1.0f - fr) + v1 * fr;     // jax linear interpolation
            gd = fmaxf(gd, EPSV);
            float g0 = expf(lg0[0]);
            float rr = 1.0f / (1.0f + expf(-rdec[0]));
            float gp = g0 * powf(rr, (float)kiter);
            float al = 1.0f / (1.0f + expf(-ralpha[0]));
            g_lamc = al * (gp / A_SCAD) + (1.0f - al) * (gd / A_SCAD);
        }
    }
    __syncthreads();                 // scan done before zeroing the hist
    for (int i = tid; i < 512; i += 256) g_hist[i] = 0;
}

// ---------------- SCAD weights + sparse propagation -------------------------
__global__ __launch_bounds__(64) void propagate_kernel(const float* __restrict__ Fin,
                                                       float* __restrict__ Fout,
                                                       float lam) {
    __shared__ float ssc[MAXDEG];
    __shared__ int   sj[MAXDEG];
    __shared__ float red[64];
    int row = blockIdx.x, t = threadIdx.x;
    int cnt = g_cnt[row];
    float lamc = g_lamc;
    float di = g_dsq[row];
    float ps = 0.0f;
    for (int e = t; e < cnt; e += 64) {
        float y  = g_y[row * MAXDEG + e];
        float ys = fmaxf(y, EPSV);
        float wm = (A_SCAD * lamc - y) / ((A_SCAD - 1.0f) * ys);
        float w  = (y <= lamc) ? 1.0f : ((y <= A_SCAD * lamc) ? wm : 0.0f);
        int j = g_cols[row * MAXDEG + e];
        ssc[e] = w / (di * g_dsq[j]);        // W * A_tilde at edge
        sj[e]  = j;
        ps += w;
    }
    red[t] = ps;
    __syncthreads();
#pragma unroll
    for (int o = 32; o; o >>= 1) {
        if (t < o) red[t] += red[t + o];
        __syncthreads();
    }
    float S = red[0];
    float Q = S / (float)(cnt + 1) + lam;    // D = cnt + 1 (self-loop)
    float acc = 0.0f;
    for (int e = 0; e < cnt; e++)
        acc = fmaf(ssc[e], Fin[sj[e] * OUTD + t], acc);
    float f0 = g_F0[row * OUTD + t];
    Fout[row * OUTD + t] = acc / Q + lam * f0 / Q;
}

// ---------------- host launcher ---------------------------------------------
extern "C" void kernel_launch(void* const* d_in, const int* in_sizes, int n_in,
                              void* d_out, int out_size) {
    const float* A      = (const float*)d_in[0];
    const float* X      = (const float*)d_in[1];
    const float* W1     = (const float*)d_in[2];
    const float* b1     = (const float*)d_in[3];
    const float* W2     = (const float*)d_in[4];
    const float* b2     = (const float*)d_in[5];
    const float* lg0    = (const float*)d_in[6];
    const float* rdec   = (const float*)d_in[7];
    const float* ralpha = (const float*)d_in[8];
    float* out = (float*)d_out;

    float *pH, *pF0, *pFA, *pFB;
    cudaGetSymbolAddress((void**)&pH,  g_H);
    cudaGetSymbolAddress((void**)&pF0, g_F0);
    cudaGetSymbolAddress((void**)&pFA, g_FA);
    cudaGetSymbolAddress((void**)&pFB, g_FB);

    reset_kernel<<<1, 1>>>();
    build_kernel<<<N_NODES, 256>>>(A);

    // F0 = relu(X @ W1 + b1) @ W2 + b2
    gemm64<true ><<<dim3(H_DIM / 64, N_NODES / 64), 256>>>(X, W1, b1, pH,
                                                           N_NODES, H_DIM, IN_DIM);
    gemm64<false><<<dim3(OUTD / 64, N_NODES / 64), 256>>>(pH, W2, b2, pF0,
                                                          N_NODES, OUTD, H_DIM);

    const int SELB = 256;
    for (int k = 0; k < PROP_STEP; k++) {
        const float* Fin = (k == 0) ? pF0 : ((k & 1) ? pFA : pFB);
        float* Fout = (k == PROP_STEP - 1) ? out : ((k & 1) ? pFB : pFA);

        normalize_kernel<<<N_NODES, 64>>>(Fin);
        ycompute_kernel<<<N_NODES, 128>>>();
        init_select_kernel<<<1, 256>>>();
        sel_kernel<16><<<SELB, 256>>>(lg0, rdec, ralpha, k);
        sel_kernel< 8><<<SELB, 256>>>(lg0, rdec, ralpha, k);
        sel_kernel< 0><<<SELB, 256>>>(lg0, rdec, ralpha, k);
        propagate_kernel<<<N_NODES, 64>>>(Fin, Fout, LAMF);
    }
}